// round 15
// baseline (speedup 1.0000x reference)
#include <cuda_runtime.h>
#include <cuda_bf16.h>
#include <math_constants.h>
#include <stdint.h>

// Problem constants
#define B 4
#define N 2048
#define DIM 1024
#define HEADS 8
#define DQK 64
#define DV 128
#define MAX_POS 10
#define SCALE 0.125f   // 64^-0.5
#define BN_ROWS (B*N)  // 8192

// -------- scratch (device globals: allocation-free) --------
__device__ float g_qk[(size_t)BN_ROWS * DIM];  // q | k packed, tf32-rounded bits
__device__ float g_v [(size_t)BN_ROWS * DIM];  // tf32-rounded bits
__device__ float g_ao[(size_t)BN_ROWS * DIM];  // attention output, plain f32
// bf16 hi/lo splits
__device__ __align__(16) __nv_bfloat16 g_xbh[(size_t)BN_ROWS * DIM];
__device__ __align__(16) __nv_bfloat16 g_xbl[(size_t)BN_ROWS * DIM];
__device__ __align__(16) __nv_bfloat16 g_abh[(size_t)BN_ROWS * DIM];
__device__ __align__(16) __nv_bfloat16 g_abl[(size_t)BN_ROWS * DIM];
// transposed+split weights [n][k]: [0]=W_qk, [1]=W_v, [2]=W_out
__device__ __align__(16) __nv_bfloat16 g_Wth[(size_t)3 * DIM * DIM];
__device__ __align__(16) __nv_bfloat16 g_Wtl[(size_t)3 * DIM * DIM];

// ---------------- helpers ----------------
__device__ __forceinline__ uint32_t f2tf32(float x) {
    uint32_t r;
    asm("cvt.rna.tf32.f32 %0, %1;" : "=r"(r) : "f"(x));
    return r;
}

__device__ __forceinline__ void mma_tf32(float c[4], const uint32_t a[4], const uint32_t b[2]) {
    asm volatile(
        "mma.sync.aligned.m16n8k8.row.col.f32.tf32.tf32.f32 "
        "{%0,%1,%2,%3}, {%4,%5,%6,%7}, {%8,%9}, {%0,%1,%2,%3};"
        : "+f"(c[0]), "+f"(c[1]), "+f"(c[2]), "+f"(c[3])
        : "r"(a[0]), "r"(a[1]), "r"(a[2]), "r"(a[3]), "r"(b[0]), "r"(b[1]));
}

__device__ __forceinline__ void mma_bf16(float c[4], const uint32_t a[4], const uint32_t b[2]) {
    asm volatile(
        "mma.sync.aligned.m16n8k16.row.col.f32.bf16.bf16.f32 "
        "{%0,%1,%2,%3}, {%4,%5,%6,%7}, {%8,%9}, {%0,%1,%2,%3};"
        : "+f"(c[0]), "+f"(c[1]), "+f"(c[2]), "+f"(c[3])
        : "r"(a[0]), "r"(a[1]), "r"(a[2]), "r"(a[3]), "r"(b[0]), "r"(b[1]));
}

__device__ __forceinline__ uint32_t smem_u32(const void* p) {
    uint32_t a;
    asm("{ .reg .u64 t; cvta.to.shared.u64 t, %1; cvt.u32.u64 %0, t; }" : "=r"(a) : "l"(p));
    return a;
}

__device__ __forceinline__ void cp16(uint32_t dst, const void* src) {
    asm volatile("cp.async.cg.shared.global [%0], [%1], 16;" :: "r"(dst), "l"(src) : "memory");
}
#define CP_COMMIT() asm volatile("cp.async.commit_group;" ::: "memory")
#define CP_WAIT1()  asm volatile("cp.async.wait_group 1;" ::: "memory")
#define CP_WAIT0()  asm volatile("cp.async.wait_group 0;" ::: "memory")

__device__ __forceinline__ void bf16_split2(float a, float b, uint32_t& h, uint32_t& l) {
    __nv_bfloat162 hp, lp;
    hp.x = __float2bfloat16(a); hp.y = __float2bfloat16(b);
    lp.x = __float2bfloat16(a - __bfloat162float(hp.x));
    lp.y = __float2bfloat16(b - __bfloat162float(hp.y));
    h = *reinterpret_cast<uint32_t*>(&hp);
    l = *reinterpret_cast<uint32_t*>(&lp);
}

// ======================= prep kernels =======================
__global__ __launch_bounds__(256)
void splitx_kernel(const float* __restrict__ X,
                   __nv_bfloat16* __restrict__ H, __nv_bfloat16* __restrict__ L)
{
    size_t i = ((size_t)blockIdx.x * 256 + threadIdx.x) * 8;
    float4 a = *(const float4*)(X + i);
    float4 b = *(const float4*)(X + i + 4);
    uint4 uh, ul;
    bf16_split2(a.x, a.y, uh.x, ul.x);
    bf16_split2(a.z, a.w, uh.y, ul.y);
    bf16_split2(b.x, b.y, uh.z, ul.z);
    bf16_split2(b.z, b.w, uh.w, ul.w);
    *(uint4*)(H + i) = uh;
    *(uint4*)(L + i) = ul;
}

__global__ __launch_bounds__(256)
void wprep_kernel(const float* __restrict__ W,
                  __nv_bfloat16* __restrict__ Wh, __nv_bfloat16* __restrict__ Wl)
{
    __shared__ float t[32][33];
    const int tx = threadIdx.x & 31, ty = threadIdx.x >> 5;
    const int n0 = blockIdx.x * 32, k0 = blockIdx.y * 32;
    #pragma unroll
    for (int i = 0; i < 4; i++)
        t[ty + 8 * i][tx] = W[(size_t)(k0 + ty + 8 * i) * 1024 + n0 + tx];
    __syncthreads();
    #pragma unroll
    for (int i = 0; i < 4; i++) {
        float x = t[tx][ty + 8 * i];
        __nv_bfloat16 h = __float2bfloat16(x);
        __nv_bfloat16 l = __float2bfloat16(x - __bfloat162float(h));
        size_t o = (size_t)(n0 + ty + 8 * i) * 1024 + k0 + tx;
        Wh[o] = h; Wl[o] = l;
    }
}

// ======================= bf16 3-term GEMM (R13, unchanged) =======================
#define RS 20
#define TILE_W (128*RS)
#define STG_W (4*TILE_W)
#define STG_B (STG_W*4)
#define GEMM_SMEM_BYTES (2*STG_B)  // 81920

__global__ __launch_bounds__(256, 2)
void gemm_bf3_kernel(const __nv_bfloat16* __restrict__ Ahp,
                     const __nv_bfloat16* __restrict__ Alp,
                     const __nv_bfloat16* __restrict__ BH0, const __nv_bfloat16* __restrict__ BL0,
                     const __nv_bfloat16* __restrict__ BH1, const __nv_bfloat16* __restrict__ BL1,
                     const float* __restrict__ bias,
                     float* __restrict__ C0, float* __restrict__ C1,
                     int nx, int round_c)
{
    extern __shared__ uint32_t smg[];
    const uint32_t sb = smem_u32(smg);

    const int tid  = threadIdx.x;
    const int lane = tid & 31;
    const int w    = tid >> 5;
    const int wm   = w >> 2;
    const int wn   = w & 3;
    const int g    = lane >> 2;
    const int r    = lane & 3;

    int bx = blockIdx.x;
    const int by = blockIdx.y;
    const __nv_bfloat16* BH = BH0;
    const __nv_bfloat16* BL = BL0;
    float* C = C0;
    if (bx >= nx) { BH = BH1; BL = BL1; C = C1; bx -= nx; }
    const int cb = bx * 128;

    const __nv_bfloat16* AbH = Ahp + (size_t)(by * 128) * DIM;
    const __nv_bfloat16* AbL = Alp + (size_t)(by * 128) * DIM;
    const __nv_bfloat16* BbH = BH + (size_t)cb * DIM;
    const __nv_bfloat16* BbL = BL + (size_t)cb * DIM;

    #define CP_AB(k0, buf) do {                                                   \
        uint32_t base = sb + (uint32_t)(buf) * STG_B;                             \
        _Pragma("unroll")                                                         \
        for (int i = 0; i < 2; i++) {                                             \
            int idx = tid + 256 * i;                                              \
            int row = idx >> 2, ch = idx & 3;                                     \
            uint32_t d = base + (uint32_t)(row * RS + ch * 4) * 4;                \
            size_t s = (size_t)row * DIM + (k0) + ch * 8;                         \
            cp16(d,                  AbH + s);                                    \
            cp16(d + TILE_W * 4,     AbL + s);                                    \
            cp16(d + 2 * TILE_W * 4, BbH + s);                                    \
            cp16(d + 3 * TILE_W * 4, BbL + s);                                    \
        }                                                                         \
        CP_COMMIT();                                                              \
    } while (0)

    float acc[4][4][4];
    #pragma unroll
    for (int mt = 0; mt < 4; mt++)
        #pragma unroll
        for (int nt = 0; nt < 4; nt++)
            #pragma unroll
            for (int i = 0; i < 4; i++) acc[mt][nt][i] = 0.f;

    const int NIT = DIM / 32;   // 32

    CP_AB(0, 0);
    CP_WAIT0();
    __syncthreads();

    for (int it = 0; it < NIT; it++) {
        const int cur = it & 1;
        const bool more = (it + 1 < NIT);
        if (more) CP_AB((it + 1) * 32, cur ^ 1);

        const uint32_t* Ah = smg + cur * STG_W;
        const uint32_t* Al = Ah + TILE_W;
        const uint32_t* Bh = Al + TILE_W;
        const uint32_t* Bl = Bh + TILE_W;

        #pragma unroll
        for (int kb = 0; kb < 16; kb += 8) {
            uint32_t bh[4][2], bl[4][2];
            #pragma unroll
            for (int nt = 0; nt < 4; nt++) {
                int n0 = (wn * 32 + nt * 8 + g) * RS + kb;
                bh[nt][0] = Bh[n0 + r];
                bh[nt][1] = Bh[n0 + r + 4];
                bl[nt][0] = Bl[n0 + r];
                bl[nt][1] = Bl[n0 + r + 4];
            }
            #pragma unroll
            for (int mt = 0; mt < 4; mt++) {
                int m0 = (wm * 64 + mt * 16 + g) * RS + kb;
                int m8 = m0 + 8 * RS;
                uint32_t aH[4], aL[4];
                aH[0] = Ah[m0 + r];     aH[1] = Ah[m8 + r];
                aH[2] = Ah[m0 + r + 4]; aH[3] = Ah[m8 + r + 4];
                aL[0] = Al[m0 + r];     aL[1] = Al[m8 + r];
                aL[2] = Al[m0 + r + 4]; aL[3] = Al[m8 + r + 4];
                #pragma unroll
                for (int nt = 0; nt < 4; nt++) {
                    mma_bf16(acc[mt][nt], aH, bl[nt]);
                    mma_bf16(acc[mt][nt], aL, bh[nt]);
                    mma_bf16(acc[mt][nt], aH, bh[nt]);
                }
            }
        }

        if (more) CP_WAIT0();
        __syncthreads();
    }

    #pragma unroll
    for (int mt = 0; mt < 4; mt++) {
        int row0 = by * 128 + wm * 64 + mt * 16 + g;
        #pragma unroll
        for (int nt = 0; nt < 4; nt++) {
            int col = cb + wn * 32 + nt * 8 + r * 2;
            float b0 = 0.f, b1 = 0.f;
            if (bias != nullptr) { b0 = bias[col]; b1 = bias[col + 1]; }
            float2 v0 = make_float2(acc[mt][nt][0] + b0, acc[mt][nt][1] + b1);
            float2 v1 = make_float2(acc[mt][nt][2] + b0, acc[mt][nt][3] + b1);
            if (round_c) {
                v0.x = __uint_as_float(f2tf32(v0.x));
                v0.y = __uint_as_float(f2tf32(v0.y));
                v1.x = __uint_as_float(f2tf32(v1.x));
                v1.y = __uint_as_float(f2tf32(v1.y));
            }
            *(float2*)(C + (size_t)row0 * DIM + col)       = v0;
            *(float2*)(C + (size_t)(row0 + 8) * DIM + col) = v1;
        }
    }
}

// ======================= Flash attention: 256 threads, 128 q-rows/CTA ==================
// Halves K/V streaming traffic vs QT=64 (each CTA amortizes the K/V stream over 2x rows).
// Per-warp math identical to R13 (8 warps x 16 q-rows).
#define AKT 64
#define QT  128
#define KS_W 68
#define VS_W 136
#define KS_BYTES (AKT * KS_W * 4)
#define VS_BYTES (AKT * VS_W * 4)
#define BUF_BYTES (KS_BYTES + VS_BYTES)
#define BUF_WORDS (BUF_BYTES / 4)
#define ATTN_SMEM_BYTES (2 * BUF_BYTES + 128)   // 104576

__global__ __launch_bounds__(256, 2)
void attn_tc_kernel(const float* __restrict__ qk, const float* __restrict__ vbuf,
                    const float* __restrict__ conv, float* __restrict__ out)
{
    extern __shared__ uint32_t smu[];
    float* Cv = (float*)(smu + 2 * BUF_WORDS);
    const uint32_t sbase = smem_u32(smu);

    const int tid  = threadIdx.x;
    const int lane = tid & 31;
    const int w    = tid >> 5;          // 0..7
    const int g    = lane >> 2;
    const int r    = lane & 3;
    const int h    = blockIdx.y;
    const int b    = blockIdx.z;
    const int i0   = blockIdx.x * QT;
    const uint32_t full = 0xffffffffu;

    if (tid < 2 * MAX_POS + 1) Cv[tid] = conv[h * (2 * MAX_POS + 1) + tid];

    uint32_t qa[8][4];
    {
        const uint32_t* q0 = (const uint32_t*)(qk + (size_t)(b * N + i0 + w * 16 + g) * DIM + h * DQK);
        const uint32_t* q1 = q0 + 8 * DIM;
        #pragma unroll
        for (int kt = 0; kt < 8; kt++) {
            qa[kt][0] = q0[kt * 8 + r];
            qa[kt][1] = q1[kt * 8 + r];
            qa[kt][2] = q0[kt * 8 + r + 4];
            qa[kt][3] = q1[kt * 8 + r + 4];
        }
    }

    // 256-thread staging: K 64x64 floats (1024 chunks, 4/thread), V 64x128 (2048, 8/thread)
    #define STAGE(j0v, bb)                                                        \
        do {                                                                      \
            uint32_t kb = sbase + (bb) * BUF_BYTES;                               \
            const float* ks = qk + (size_t)(b * N + (j0v)) * DIM                  \
                              + HEADS * DQK + h * DQK;                            \
            _Pragma("unroll")                                                     \
            for (int i = 0; i < 4; i++) {                                         \
                int idx = tid + 256 * i;                                          \
                int row = idx >> 4, c4 = (idx & 15) << 2;                         \
                cp16(kb + (uint32_t)(row * KS_W + c4) * 4,                        \
                     ks + (size_t)row * DIM + c4);                                \
            }                                                                     \
            uint32_t vb = kb + KS_BYTES;                                          \
            const float* vs = vbuf + (size_t)(b * N + (j0v)) * DIM + h * DV;      \
            _Pragma("unroll")                                                     \
            for (int i = 0; i < 8; i++) {                                         \
                int idx = tid + 256 * i;                                          \
                int row = idx >> 5, c4 = (idx & 31) << 2;                         \
                cp16(vb + (uint32_t)(row * VS_W + c4) * 4,                        \
                     vs + (size_t)row * DIM + c4);                                \
            }                                                                     \
            CP_COMMIT();                                                          \
        } while (0)

    float l_lo = 0.f, l_hi = 0.f;
    float oacc[8][2][4];
    #pragma unroll
    for (int mt = 0; mt < 8; mt++)
        #pragma unroll
        for (int nt = 0; nt < 2; nt++)
            #pragma unroll
            for (int i = 0; i < 4; i++) oacc[mt][nt][i] = 0.f;

    const int ilo = i0 + w * 16 + g;
    const int ihi = ilo + 8;
    const int srcA = (lane & ~3) | (r >> 1);
    const int srcB = srcA + 2;
    const bool pr  = (r & 1);

    STAGE(0, 0);

    const int NJ = N / AKT;   // 32
    for (int jt = 0; jt < NJ; jt++) {
        const int buf = jt & 1;
        if (jt + 1 < NJ) { STAGE((jt + 1) * AKT, buf ^ 1); CP_WAIT1(); }
        else             { CP_WAIT0(); }
        __syncthreads();

        const uint32_t* Ks = smu + buf * BUF_WORDS;
        const uint32_t* Vs = Ks + KS_BYTES / 4;
        const int j0 = jt * AKT;

        float sacc[8][4];
        #pragma unroll
        for (int nt = 0; nt < 8; nt++)
            #pragma unroll
            for (int i = 0; i < 4; i++) sacc[nt][i] = 0.f;

        #pragma unroll
        for (int kt = 0; kt < 8; kt++) {
            #pragma unroll
            for (int nt = 0; nt < 8; nt++) {
                uint32_t bf[2];
                bf[0] = Ks[(nt * 8 + g) * KS_W + kt * 8 + r];
                bf[1] = Ks[(nt * 8 + g) * KS_W + kt * 8 + r + 4];
                mma_tf32(sacc[nt], qa[kt], bf);
            }
        }

        uint32_t Pf[8][4];
        float ls_lo = 0.f, ls_hi = 0.f;
        #pragma unroll
        for (int nt = 0; nt < 8; nt++) {
            int j = j0 + nt * 8 + 2 * r;
            int d00 = min(max(j     - ilo, -MAX_POS), MAX_POS) + MAX_POS;
            int d01 = min(max(j + 1 - ilo, -MAX_POS), MAX_POS) + MAX_POS;
            int d10 = min(max(j     - ihi, -MAX_POS), MAX_POS) + MAX_POS;
            int d11 = min(max(j + 1 - ihi, -MAX_POS), MAX_POS) + MAX_POS;
            float p0 = __expf(sacc[nt][0] * SCALE + Cv[d00]);
            float p1 = __expf(sacc[nt][1] * SCALE + Cv[d01]);
            float p2 = __expf(sacc[nt][2] * SCALE + Cv[d10]);
            float p3 = __expf(sacc[nt][3] * SCALE + Cv[d11]);
            ls_lo += p0 + p1;
            ls_hi += p2 + p3;
            Pf[nt][0] = f2tf32(p0); Pf[nt][1] = f2tf32(p1);
            Pf[nt][2] = f2tf32(p2); Pf[nt][3] = f2tf32(p3);
        }
        l_lo += ls_lo;
        l_hi += ls_hi;

        #pragma unroll
        for (int kt = 0; kt < 8; kt++) {
            uint32_t s0 = __shfl_sync(full, Pf[kt][0], srcA);
            uint32_t s1 = __shfl_sync(full, Pf[kt][1], srcA);
            uint32_t t0 = __shfl_sync(full, Pf[kt][0], srcB);
            uint32_t t1 = __shfl_sync(full, Pf[kt][1], srcB);
            uint32_t bl2[2];
            bl2[0] = pr ? s1 : s0;
            bl2[1] = pr ? t1 : t0;
            uint32_t s2 = __shfl_sync(full, Pf[kt][2], srcA);
            uint32_t s3 = __shfl_sync(full, Pf[kt][3], srcA);
            uint32_t t2 = __shfl_sync(full, Pf[kt][2], srcB);
            uint32_t t3 = __shfl_sync(full, Pf[kt][3], srcB);
            uint32_t bh2[2];
            bh2[0] = pr ? s3 : s2;
            bh2[1] = pr ? t3 : t2;
            #pragma unroll
            for (int mt = 0; mt < 8; mt++) {
                uint32_t vf[4];
                vf[0] = Vs[(kt * 8 + r)     * VS_W + mt * 16 + g];
                vf[1] = Vs[(kt * 8 + r)     * VS_W + mt * 16 + 8 + g];
                vf[2] = Vs[(kt * 8 + r + 4) * VS_W + mt * 16 + g];
                vf[3] = Vs[(kt * 8 + r + 4) * VS_W + mt * 16 + 8 + g];
                mma_tf32(oacc[mt][0], vf, bl2);
                mma_tf32(oacc[mt][1], vf, bh2);
            }
        }
        __syncthreads();
    }

    l_lo += __shfl_xor_sync(full, l_lo, 1);
    l_lo += __shfl_xor_sync(full, l_lo, 2);
    l_hi += __shfl_xor_sync(full, l_hi, 1);
    l_hi += __shfl_xor_sync(full, l_hi, 2);
    float inv_lo = 1.f / l_lo;
    float inv_hi = 1.f / l_hi;
    float iq0  = __shfl_sync(full, inv_lo, 8 * r);
    float iq1  = __shfl_sync(full, inv_lo, 8 * r + 4);
    float iq0h = __shfl_sync(full, inv_hi, 8 * r);
    float iq1h = __shfl_sync(full, inv_hi, 8 * r + 4);

    const size_t rbase = (size_t)(b * N + i0 + w * 16);
    #pragma unroll
    for (int mt = 0; mt < 8; mt++) {
        int dcol = h * DV + mt * 16 + g;
        out[(rbase + 2 * r    ) * DIM + dcol    ] = oacc[mt][0][0] * iq0;
        out[(rbase + 2 * r + 1) * DIM + dcol    ] = oacc[mt][0][1] * iq1;
        out[(rbase + 2 * r    ) * DIM + dcol + 8] = oacc[mt][0][2] * iq0;
        out[(rbase + 2 * r + 1) * DIM + dcol + 8] = oacc[mt][0][3] * iq1;
        out[(rbase + 8 + 2 * r    ) * DIM + dcol    ] = oacc[mt][1][0] * iq0h;
        out[(rbase + 8 + 2 * r + 1) * DIM + dcol    ] = oacc[mt][1][1] * iq1h;
        out[(rbase + 8 + 2 * r    ) * DIM + dcol + 8] = oacc[mt][1][2] * iq0h;
        out[(rbase + 8 + 2 * r + 1) * DIM + dcol + 8] = oacc[mt][1][3] * iq1h;
    }
}

// ======================= launch =======================
extern "C" void kernel_launch(void* const* d_in, const int* in_sizes, int n_in,
                              void* d_out, int out_size)
{
    const float* x     = (const float*)d_in[0];
    // d_in[1] = mask (unused by the reference)
    const float* W_qk  = (const float*)d_in[2];
    const float* W_v   = (const float*)d_in[3];
    const float* W_out = (const float*)d_in[4];
    const float* b_out = (const float*)d_in[5];
    const float* conv  = (const float*)d_in[6];
    float* out = (float*)d_out;

    float *qk_p, *v_p, *ao_p;
    cudaGetSymbolAddress((void**)&qk_p, g_qk);
    cudaGetSymbolAddress((void**)&v_p,  g_v);
    cudaGetSymbolAddress((void**)&ao_p, g_ao);
    __nv_bfloat16 *xbh, *xbl, *abh, *abl, *wth, *wtl;
    cudaGetSymbolAddress((void**)&xbh, g_xbh);
    cudaGetSymbolAddress((void**)&xbl, g_xbl);
    cudaGetSymbolAddress((void**)&abh, g_abh);
    cudaGetSymbolAddress((void**)&abl, g_abl);
    cudaGetSymbolAddress((void**)&wth, g_Wth);
    cudaGetSymbolAddress((void**)&wtl, g_Wtl);

    cudaFuncSetAttribute(gemm_bf3_kernel, cudaFuncAttributeMaxDynamicSharedMemorySize,
                         GEMM_SMEM_BYTES);
    cudaFuncSetAttribute(attn_tc_kernel, cudaFuncAttributeMaxDynamicSharedMemorySize,
                         ATTN_SMEM_BYTES);

    const size_t WSZ = (size_t)DIM * DIM;

    // 0) prep: split x; transpose+split weights
    splitx_kernel<<<BN_ROWS * DIM / 2048, 256>>>(x, xbh, xbl);
    dim3 wgrid(32, 32);
    wprep_kernel<<<wgrid, 256>>>(W_qk,  wth,           wtl);
    wprep_kernel<<<wgrid, 256>>>(W_v,   wth + WSZ,     wtl + WSZ);
    wprep_kernel<<<wgrid, 256>>>(W_out, wth + 2 * WSZ, wtl + 2 * WSZ);

    // 1+2) fused qkv (single launch): bx 0..7 -> g_qk (W_qk), bx 8..15 -> g_v (W_v)
    dim3 qkv_grid(16, 64);
    gemm_bf3_kernel<<<qkv_grid, 256, GEMM_SMEM_BYTES>>>(
        xbh, xbl, wth, wtl, wth + WSZ, wtl + WSZ, nullptr, qk_p, v_p, 8, 1);

    // 3) attention -> g_ao (plain f32); 512 CTAs of 256 threads
    dim3 attn_grid(N / QT, HEADS, B);   // (16, 8, 4)
    attn_tc_kernel<<<attn_grid, 256, ATTN_SMEM_BYTES>>>(qk_p, v_p, conv, ao_p);

    // 3b) split ao to bf16 hi/lo
    splitx_kernel<<<BN_ROWS * DIM / 2048, 256>>>(ao_p, abh, abl);

    // 4) out = ao @ W_out + b_out (full f32 output)
    dim3 out_grid(8, 64);
    gemm_bf3_kernel<<<out_grid, 256, GEMM_SMEM_BYTES>>>(
        abh, abl, wth + 2 * WSZ, wtl + 2 * WSZ, wth + 2 * WSZ, wtl + 2 * WSZ,
        b_out, out, out, 8, 0);
}

// round 16
// speedup vs baseline: 1.1580x; 1.1580x over previous
#include <cuda_runtime.h>
#include <cuda_bf16.h>
#include <math_constants.h>
#include <stdint.h>

// Problem constants
#define B 4
#define N 2048
#define DIM 1024
#define HEADS 8
#define DQK 64
#define DV 128
#define MAX_POS 10
#define SCALE 0.125f   // 64^-0.5
#define BN_ROWS (B*N)  // 8192

// -------- scratch (device globals: allocation-free) --------
__device__ float g_qk[(size_t)BN_ROWS * DIM];  // q | k packed, tf32-rounded bits
__device__ float g_v [(size_t)BN_ROWS * DIM];  // tf32-rounded bits
__device__ float g_ao[(size_t)BN_ROWS * DIM];  // attention output, plain f32
// bf16 hi/lo splits
__device__ __align__(16) __nv_bfloat16 g_xbh[(size_t)BN_ROWS * DIM];
__device__ __align__(16) __nv_bfloat16 g_xbl[(size_t)BN_ROWS * DIM];
__device__ __align__(16) __nv_bfloat16 g_abh[(size_t)BN_ROWS * DIM];
__device__ __align__(16) __nv_bfloat16 g_abl[(size_t)BN_ROWS * DIM];
// transposed+split weights [n][k]: [0]=W_qk, [1]=W_v, [2]=W_out
__device__ __align__(16) __nv_bfloat16 g_Wth[(size_t)3 * DIM * DIM];
__device__ __align__(16) __nv_bfloat16 g_Wtl[(size_t)3 * DIM * DIM];

// ---------------- helpers ----------------
__device__ __forceinline__ uint32_t f2tf32(float x) {
    uint32_t r;
    asm("cvt.rna.tf32.f32 %0, %1;" : "=r"(r) : "f"(x));
    return r;
}

__device__ __forceinline__ void mma_tf32(float c[4], const uint32_t a[4], const uint32_t b[2]) {
    asm volatile(
        "mma.sync.aligned.m16n8k8.row.col.f32.tf32.tf32.f32 "
        "{%0,%1,%2,%3}, {%4,%5,%6,%7}, {%8,%9}, {%0,%1,%2,%3};"
        : "+f"(c[0]), "+f"(c[1]), "+f"(c[2]), "+f"(c[3])
        : "r"(a[0]), "r"(a[1]), "r"(a[2]), "r"(a[3]), "r"(b[0]), "r"(b[1]));
}

__device__ __forceinline__ void mma_bf16(float c[4], const uint32_t a[4], const uint32_t b[2]) {
    asm volatile(
        "mma.sync.aligned.m16n8k16.row.col.f32.bf16.bf16.f32 "
        "{%0,%1,%2,%3}, {%4,%5,%6,%7}, {%8,%9}, {%0,%1,%2,%3};"
        : "+f"(c[0]), "+f"(c[1]), "+f"(c[2]), "+f"(c[3])
        : "r"(a[0]), "r"(a[1]), "r"(a[2]), "r"(a[3]), "r"(b[0]), "r"(b[1]));
}

__device__ __forceinline__ uint32_t smem_u32(const void* p) {
    uint32_t a;
    asm("{ .reg .u64 t; cvta.to.shared.u64 t, %1; cvt.u32.u64 %0, t; }" : "=r"(a) : "l"(p));
    return a;
}

__device__ __forceinline__ void cp16(uint32_t dst, const void* src) {
    asm volatile("cp.async.cg.shared.global [%0], [%1], 16;" :: "r"(dst), "l"(src) : "memory");
}
#define CP_COMMIT() asm volatile("cp.async.commit_group;" ::: "memory")
#define CP_WAIT1()  asm volatile("cp.async.wait_group 1;" ::: "memory")
#define CP_WAIT0()  asm volatile("cp.async.wait_group 0;" ::: "memory")

__device__ __forceinline__ void bf16_split2(float a, float b, uint32_t& h, uint32_t& l) {
    __nv_bfloat162 hp, lp;
    hp.x = __float2bfloat16(a); hp.y = __float2bfloat16(b);
    lp.x = __float2bfloat16(a - __bfloat162float(hp.x));
    lp.y = __float2bfloat16(b - __bfloat162float(hp.y));
    h = *reinterpret_cast<uint32_t*>(&hp);
    l = *reinterpret_cast<uint32_t*>(&lp);
}

// ======================= prep kernels =======================
__global__ __launch_bounds__(256)
void splitx_kernel(const float* __restrict__ X,
                   __nv_bfloat16* __restrict__ H, __nv_bfloat16* __restrict__ L)
{
    size_t i = ((size_t)blockIdx.x * 256 + threadIdx.x) * 8;
    float4 a = *(const float4*)(X + i);
    float4 b = *(const float4*)(X + i + 4);
    uint4 uh, ul;
    bf16_split2(a.x, a.y, uh.x, ul.x);
    bf16_split2(a.z, a.w, uh.y, ul.y);
    bf16_split2(b.x, b.y, uh.z, ul.z);
    bf16_split2(b.z, b.w, uh.w, ul.w);
    *(uint4*)(H + i) = uh;
    *(uint4*)(L + i) = ul;
}

__global__ __launch_bounds__(256)
void wprep_kernel(const float* __restrict__ W,
                  __nv_bfloat16* __restrict__ Wh, __nv_bfloat16* __restrict__ Wl)
{
    __shared__ float t[32][33];
    const int tx = threadIdx.x & 31, ty = threadIdx.x >> 5;
    const int n0 = blockIdx.x * 32, k0 = blockIdx.y * 32;
    #pragma unroll
    for (int i = 0; i < 4; i++)
        t[ty + 8 * i][tx] = W[(size_t)(k0 + ty + 8 * i) * 1024 + n0 + tx];
    __syncthreads();
    #pragma unroll
    for (int i = 0; i < 4; i++) {
        float x = t[tx][ty + 8 * i];
        __nv_bfloat16 h = __float2bfloat16(x);
        __nv_bfloat16 l = __float2bfloat16(x - __bfloat162float(h));
        size_t o = (size_t)(n0 + ty + 8 * i) * 1024 + k0 + tx;
        Wh[o] = h; Wl[o] = l;
    }
}

// ======================= bf16 3-term GEMM (R13, unchanged) =======================
#define RS 20
#define TILE_W (128*RS)
#define STG_W (4*TILE_W)
#define STG_B (STG_W*4)
#define GEMM_SMEM_BYTES (2*STG_B)  // 81920

__global__ __launch_bounds__(256, 2)
void gemm_bf3_kernel(const __nv_bfloat16* __restrict__ Ahp,
                     const __nv_bfloat16* __restrict__ Alp,
                     const __nv_bfloat16* __restrict__ BH0, const __nv_bfloat16* __restrict__ BL0,
                     const __nv_bfloat16* __restrict__ BH1, const __nv_bfloat16* __restrict__ BL1,
                     const float* __restrict__ bias,
                     float* __restrict__ C0, float* __restrict__ C1,
                     int nx, int round_c)
{
    extern __shared__ uint32_t smg[];
    const uint32_t sb = smem_u32(smg);

    const int tid  = threadIdx.x;
    const int lane = tid & 31;
    const int w    = tid >> 5;
    const int wm   = w >> 2;
    const int wn   = w & 3;
    const int g    = lane >> 2;
    const int r    = lane & 3;

    int bx = blockIdx.x;
    const int by = blockIdx.y;
    const __nv_bfloat16* BH = BH0;
    const __nv_bfloat16* BL = BL0;
    float* C = C0;
    if (bx >= nx) { BH = BH1; BL = BL1; C = C1; bx -= nx; }
    const int cb = bx * 128;

    const __nv_bfloat16* AbH = Ahp + (size_t)(by * 128) * DIM;
    const __nv_bfloat16* AbL = Alp + (size_t)(by * 128) * DIM;
    const __nv_bfloat16* BbH = BH + (size_t)cb * DIM;
    const __nv_bfloat16* BbL = BL + (size_t)cb * DIM;

    #define CP_AB(k0, buf) do {                                                   \
        uint32_t base = sb + (uint32_t)(buf) * STG_B;                             \
        _Pragma("unroll")                                                         \
        for (int i = 0; i < 2; i++) {                                             \
            int idx = tid + 256 * i;                                              \
            int row = idx >> 2, ch = idx & 3;                                     \
            uint32_t d = base + (uint32_t)(row * RS + ch * 4) * 4;                \
            size_t s = (size_t)row * DIM + (k0) + ch * 8;                         \
            cp16(d,                  AbH + s);                                    \
            cp16(d + TILE_W * 4,     AbL + s);                                    \
            cp16(d + 2 * TILE_W * 4, BbH + s);                                    \
            cp16(d + 3 * TILE_W * 4, BbL + s);                                    \
        }                                                                         \
        CP_COMMIT();                                                              \
    } while (0)

    float acc[4][4][4];
    #pragma unroll
    for (int mt = 0; mt < 4; mt++)
        #pragma unroll
        for (int nt = 0; nt < 4; nt++)
            #pragma unroll
            for (int i = 0; i < 4; i++) acc[mt][nt][i] = 0.f;

    const int NIT = DIM / 32;   // 32

    CP_AB(0, 0);
    CP_WAIT0();
    __syncthreads();

    for (int it = 0; it < NIT; it++) {
        const int cur = it & 1;
        const bool more = (it + 1 < NIT);
        if (more) CP_AB((it + 1) * 32, cur ^ 1);

        const uint32_t* Ah = smg + cur * STG_W;
        const uint32_t* Al = Ah + TILE_W;
        const uint32_t* Bh = Al + TILE_W;
        const uint32_t* Bl = Bh + TILE_W;

        #pragma unroll
        for (int kb = 0; kb < 16; kb += 8) {
            uint32_t bh[4][2], bl[4][2];
            #pragma unroll
            for (int nt = 0; nt < 4; nt++) {
                int n0 = (wn * 32 + nt * 8 + g) * RS + kb;
                bh[nt][0] = Bh[n0 + r];
                bh[nt][1] = Bh[n0 + r + 4];
                bl[nt][0] = Bl[n0 + r];
                bl[nt][1] = Bl[n0 + r + 4];
            }
            #pragma unroll
            for (int mt = 0; mt < 4; mt++) {
                int m0 = (wm * 64 + mt * 16 + g) * RS + kb;
                int m8 = m0 + 8 * RS;
                uint32_t aH[4], aL[4];
                aH[0] = Ah[m0 + r];     aH[1] = Ah[m8 + r];
                aH[2] = Ah[m0 + r + 4]; aH[3] = Ah[m8 + r + 4];
                aL[0] = Al[m0 + r];     aL[1] = Al[m8 + r];
                aL[2] = Al[m0 + r + 4]; aL[3] = Al[m8 + r + 4];
                #pragma unroll
                for (int nt = 0; nt < 4; nt++) {
                    mma_bf16(acc[mt][nt], aH, bl[nt]);
                    mma_bf16(acc[mt][nt], aL, bh[nt]);
                    mma_bf16(acc[mt][nt], aH, bh[nt]);
                }
            }
        }

        if (more) CP_WAIT0();
        __syncthreads();
    }

    #pragma unroll
    for (int mt = 0; mt < 4; mt++) {
        int row0 = by * 128 + wm * 64 + mt * 16 + g;
        #pragma unroll
        for (int nt = 0; nt < 4; nt++) {
            int col = cb + wn * 32 + nt * 8 + r * 2;
            float b0 = 0.f, b1 = 0.f;
            if (bias != nullptr) { b0 = bias[col]; b1 = bias[col + 1]; }
            float2 v0 = make_float2(acc[mt][nt][0] + b0, acc[mt][nt][1] + b1);
            float2 v1 = make_float2(acc[mt][nt][2] + b0, acc[mt][nt][3] + b1);
            if (round_c) {
                v0.x = __uint_as_float(f2tf32(v0.x));
                v0.y = __uint_as_float(f2tf32(v0.y));
                v1.x = __uint_as_float(f2tf32(v1.x));
                v1.y = __uint_as_float(f2tf32(v1.y));
            }
            *(float2*)(C + (size_t)row0 * DIM + col)       = v0;
            *(float2*)(C + (size_t)(row0 + 8) * DIM + col) = v1;
        }
    }
}

// ======================= Flash attention: 256 threads, 128 q-rows, occ 1 ===============
// K/V stream amortized over 128 q-rows (half the traffic of QT=64). __launch_bounds__
// (256,1) keeps the 256-register budget -> no spills (R15's failure mode).
#define AKT 64
#define QT  128
#define KS_W 68
#define VS_W 136
#define KS_BYTES (AKT * KS_W * 4)
#define VS_BYTES (AKT * VS_W * 4)
#define BUF_BYTES (KS_BYTES + VS_BYTES)
#define BUF_WORDS (BUF_BYTES / 4)
#define ATTN_SMEM_BYTES (2 * BUF_BYTES + 128)   // 104576

__global__ __launch_bounds__(256, 1)
void attn_tc_kernel(const float* __restrict__ qk, const float* __restrict__ vbuf,
                    const float* __restrict__ conv, float* __restrict__ out)
{
    extern __shared__ uint32_t smu[];
    float* Cv = (float*)(smu + 2 * BUF_WORDS);
    const uint32_t sbase = smem_u32(smu);

    const int tid  = threadIdx.x;
    const int lane = tid & 31;
    const int w    = tid >> 5;          // 0..7
    const int g    = lane >> 2;
    const int r    = lane & 3;
    const int h    = blockIdx.y;
    const int b    = blockIdx.z;
    const int i0   = blockIdx.x * QT;
    const uint32_t full = 0xffffffffu;

    if (tid < 2 * MAX_POS + 1) Cv[tid] = conv[h * (2 * MAX_POS + 1) + tid];

    uint32_t qa[8][4];
    {
        const uint32_t* q0 = (const uint32_t*)(qk + (size_t)(b * N + i0 + w * 16 + g) * DIM + h * DQK);
        const uint32_t* q1 = q0 + 8 * DIM;
        #pragma unroll
        for (int kt = 0; kt < 8; kt++) {
            qa[kt][0] = q0[kt * 8 + r];
            qa[kt][1] = q1[kt * 8 + r];
            qa[kt][2] = q0[kt * 8 + r + 4];
            qa[kt][3] = q1[kt * 8 + r + 4];
        }
    }

    // 256-thread staging: K 64x64 floats (1024 chunks, 4/thread), V 64x128 (2048, 8/thread)
    #define STAGE(j0v, bb)                                                        \
        do {                                                                      \
            uint32_t kb = sbase + (bb) * BUF_BYTES;                               \
            const float* ks = qk + (size_t)(b * N + (j0v)) * DIM                  \
                              + HEADS * DQK + h * DQK;                            \
            _Pragma("unroll")                                                     \
            for (int i = 0; i < 4; i++) {                                         \
                int idx = tid + 256 * i;                                          \
                int row = idx >> 4, c4 = (idx & 15) << 2;                         \
                cp16(kb + (uint32_t)(row * KS_W + c4) * 4,                        \
                     ks + (size_t)row * DIM + c4);                                \
            }                                                                     \
            uint32_t vb = kb + KS_BYTES;                                          \
            const float* vs = vbuf + (size_t)(b * N + (j0v)) * DIM + h * DV;      \
            _Pragma("unroll")                                                     \
            for (int i = 0; i < 8; i++) {                                         \
                int idx = tid + 256 * i;                                          \
                int row = idx >> 5, c4 = (idx & 31) << 2;                         \
                cp16(vb + (uint32_t)(row * VS_W + c4) * 4,                        \
                     vs + (size_t)row * DIM + c4);                                \
            }                                                                     \
            CP_COMMIT();                                                          \
        } while (0)

    float l_lo = 0.f, l_hi = 0.f;
    float oacc[8][2][4];
    #pragma unroll
    for (int mt = 0; mt < 8; mt++)
        #pragma unroll
        for (int nt = 0; nt < 2; nt++)
            #pragma unroll
            for (int i = 0; i < 4; i++) oacc[mt][nt][i] = 0.f;

    const int ilo = i0 + w * 16 + g;
    const int ihi = ilo + 8;
    const int srcA = (lane & ~3) | (r >> 1);
    const int srcB = srcA + 2;
    const bool pr  = (r & 1);

    STAGE(0, 0);

    const int NJ = N / AKT;   // 32
    for (int jt = 0; jt < NJ; jt++) {
        const int buf = jt & 1;
        if (jt + 1 < NJ) { STAGE((jt + 1) * AKT, buf ^ 1); CP_WAIT1(); }
        else             { CP_WAIT0(); }
        __syncthreads();

        const uint32_t* Ks = smu + buf * BUF_WORDS;
        const uint32_t* Vs = Ks + KS_BYTES / 4;
        const int j0 = jt * AKT;

        float sacc[8][4];
        #pragma unroll
        for (int nt = 0; nt < 8; nt++)
            #pragma unroll
            for (int i = 0; i < 4; i++) sacc[nt][i] = 0.f;

        #pragma unroll
        for (int kt = 0; kt < 8; kt++) {
            #pragma unroll
            for (int nt = 0; nt < 8; nt++) {
                uint32_t bf[2];
                bf[0] = Ks[(nt * 8 + g) * KS_W + kt * 8 + r];
                bf[1] = Ks[(nt * 8 + g) * KS_W + kt * 8 + r + 4];
                mma_tf32(sacc[nt], qa[kt], bf);
            }
        }

        uint32_t Pf[8][4];
        float ls_lo = 0.f, ls_hi = 0.f;
        #pragma unroll
        for (int nt = 0; nt < 8; nt++) {
            int j = j0 + nt * 8 + 2 * r;
            int d00 = min(max(j     - ilo, -MAX_POS), MAX_POS) + MAX_POS;
            int d01 = min(max(j + 1 - ilo, -MAX_POS), MAX_POS) + MAX_POS;
            int d10 = min(max(j     - ihi, -MAX_POS), MAX_POS) + MAX_POS;
            int d11 = min(max(j + 1 - ihi, -MAX_POS), MAX_POS) + MAX_POS;
            float p0 = __expf(sacc[nt][0] * SCALE + Cv[d00]);
            float p1 = __expf(sacc[nt][1] * SCALE + Cv[d01]);
            float p2 = __expf(sacc[nt][2] * SCALE + Cv[d10]);
            float p3 = __expf(sacc[nt][3] * SCALE + Cv[d11]);
            ls_lo += p0 + p1;
            ls_hi += p2 + p3;
            Pf[nt][0] = f2tf32(p0); Pf[nt][1] = f2tf32(p1);
            Pf[nt][2] = f2tf32(p2); Pf[nt][3] = f2tf32(p3);
        }
        l_lo += ls_lo;
        l_hi += ls_hi;

        #pragma unroll
        for (int kt = 0; kt < 8; kt++) {
            uint32_t s0 = __shfl_sync(full, Pf[kt][0], srcA);
            uint32_t s1 = __shfl_sync(full, Pf[kt][1], srcA);
            uint32_t t0 = __shfl_sync(full, Pf[kt][0], srcB);
            uint32_t t1 = __shfl_sync(full, Pf[kt][1], srcB);
            uint32_t bl2[2];
            bl2[0] = pr ? s1 : s0;
            bl2[1] = pr ? t1 : t0;
            uint32_t s2 = __shfl_sync(full, Pf[kt][2], srcA);
            uint32_t s3 = __shfl_sync(full, Pf[kt][3], srcA);
            uint32_t t2 = __shfl_sync(full, Pf[kt][2], srcB);
            uint32_t t3 = __shfl_sync(full, Pf[kt][3], srcB);
            uint32_t bh2[2];
            bh2[0] = pr ? s3 : s2;
            bh2[1] = pr ? t3 : t2;
            #pragma unroll
            for (int mt = 0; mt < 8; mt++) {
                uint32_t vf[4];
                vf[0] = Vs[(kt * 8 + r)     * VS_W + mt * 16 + g];
                vf[1] = Vs[(kt * 8 + r)     * VS_W + mt * 16 + 8 + g];
                vf[2] = Vs[(kt * 8 + r + 4) * VS_W + mt * 16 + g];
                vf[3] = Vs[(kt * 8 + r + 4) * VS_W + mt * 16 + 8 + g];
                mma_tf32(oacc[mt][0], vf, bl2);
                mma_tf32(oacc[mt][1], vf, bh2);
            }
        }
        __syncthreads();
    }

    l_lo += __shfl_xor_sync(full, l_lo, 1);
    l_lo += __shfl_xor_sync(full, l_lo, 2);
    l_hi += __shfl_xor_sync(full, l_hi, 1);
    l_hi += __shfl_xor_sync(full, l_hi, 2);
    float inv_lo = 1.f / l_lo;
    float inv_hi = 1.f / l_hi;
    float iq0  = __shfl_sync(full, inv_lo, 8 * r);
    float iq1  = __shfl_sync(full, inv_lo, 8 * r + 4);
    float iq0h = __shfl_sync(full, inv_hi, 8 * r);
    float iq1h = __shfl_sync(full, inv_hi, 8 * r + 4);

    const size_t rbase = (size_t)(b * N + i0 + w * 16);
    #pragma unroll
    for (int mt = 0; mt < 8; mt++) {
        int dcol = h * DV + mt * 16 + g;
        out[(rbase + 2 * r    ) * DIM + dcol    ] = oacc[mt][0][0] * iq0;
        out[(rbase + 2 * r + 1) * DIM + dcol    ] = oacc[mt][0][1] * iq1;
        out[(rbase + 2 * r    ) * DIM + dcol + 8] = oacc[mt][0][2] * iq0;
        out[(rbase + 2 * r + 1) * DIM + dcol + 8] = oacc[mt][0][3] * iq1;
        out[(rbase + 8 + 2 * r    ) * DIM + dcol    ] = oacc[mt][1][0] * iq0h;
        out[(rbase + 8 + 2 * r + 1) * DIM + dcol    ] = oacc[mt][1][1] * iq1h;
        out[(rbase + 8 + 2 * r    ) * DIM + dcol + 8] = oacc[mt][1][2] * iq0h;
        out[(rbase + 8 + 2 * r + 1) * DIM + dcol + 8] = oacc[mt][1][3] * iq1h;
    }
}

// ======================= launch =======================
extern "C" void kernel_launch(void* const* d_in, const int* in_sizes, int n_in,
                              void* d_out, int out_size)
{
    const float* x     = (const float*)d_in[0];
    // d_in[1] = mask (unused by the reference)
    const float* W_qk  = (const float*)d_in[2];
    const float* W_v   = (const float*)d_in[3];
    const float* W_out = (const float*)d_in[4];
    const float* b_out = (const float*)d_in[5];
    const float* conv  = (const float*)d_in[6];
    float* out = (float*)d_out;

    float *qk_p, *v_p, *ao_p;
    cudaGetSymbolAddress((void**)&qk_p, g_qk);
    cudaGetSymbolAddress((void**)&v_p,  g_v);
    cudaGetSymbolAddress((void**)&ao_p, g_ao);
    __nv_bfloat16 *xbh, *xbl, *abh, *abl, *wth, *wtl;
    cudaGetSymbolAddress((void**)&xbh, g_xbh);
    cudaGetSymbolAddress((void**)&xbl, g_xbl);
    cudaGetSymbolAddress((void**)&abh, g_abh);
    cudaGetSymbolAddress((void**)&abl, g_abl);
    cudaGetSymbolAddress((void**)&wth, g_Wth);
    cudaGetSymbolAddress((void**)&wtl, g_Wtl);

    cudaFuncSetAttribute(gemm_bf3_kernel, cudaFuncAttributeMaxDynamicSharedMemorySize,
                         GEMM_SMEM_BYTES);
    cudaFuncSetAttribute(attn_tc_kernel, cudaFuncAttributeMaxDynamicSharedMemorySize,
                         ATTN_SMEM_BYTES);

    const size_t WSZ = (size_t)DIM * DIM;

    // 0) prep: split x; transpose+split weights
    splitx_kernel<<<BN_ROWS * DIM / 2048, 256>>>(x, xbh, xbl);
    dim3 wgrid(32, 32);
    wprep_kernel<<<wgrid, 256>>>(W_qk,  wth,           wtl);
    wprep_kernel<<<wgrid, 256>>>(W_v,   wth + WSZ,     wtl + WSZ);
    wprep_kernel<<<wgrid, 256>>>(W_out, wth + 2 * WSZ, wtl + 2 * WSZ);

    // 1+2) fused qkv (single launch): bx 0..7 -> g_qk (W_qk), bx 8..15 -> g_v (W_v)
    dim3 qkv_grid(16, 64);
    gemm_bf3_kernel<<<qkv_grid, 256, GEMM_SMEM_BYTES>>>(
        xbh, xbl, wth, wtl, wth + WSZ, wtl + WSZ, nullptr, qk_p, v_p, 8, 1);

    // 3) attention -> g_ao (plain f32); 512 CTAs of 256 threads, occ 1
    dim3 attn_grid(N / QT, HEADS, B);   // (16, 8, 4)
    attn_tc_kernel<<<attn_grid, 256, ATTN_SMEM_BYTES>>>(qk_p, v_p, conv, ao_p);

    // 3b) split ao to bf16 hi/lo
    splitx_kernel<<<BN_ROWS * DIM / 2048, 256>>>(ao_p, abh, abl);

    // 4) out = ao @ W_out + b_out (full f32 output)
    dim3 out_grid(8, 64);
    gemm_bf3_kernel<<<out_grid, 256, GEMM_SMEM_BYTES>>>(
        abh, abl, wth + 2 * WSZ, wtl + 2 * WSZ, wth + 2 * WSZ, wtl + 2 * WSZ,
        b_out, out, out, 8, 0);
}

// round 17
// speedup vs baseline: 1.2132x; 1.0476x over previous
#include <cuda_runtime.h>
#include <cuda_bf16.h>
#include <math_constants.h>
#include <stdint.h>

// Problem constants
#define B 4
#define N 2048
#define DIM 1024
#define HEADS 8
#define DQK 64
#define DV 128
#define MAX_POS 10
#define SCALE 0.125f   // 64^-0.5
#define BN_ROWS (B*N)  // 8192

// -------- scratch (device globals: allocation-free) --------
__device__ float g_qk[(size_t)BN_ROWS * DIM];  // q | k packed, tf32-rounded bits
__device__ float g_v [(size_t)BN_ROWS * DIM];  // tf32-rounded bits
// bf16 hi/lo splits
__device__ __align__(16) __nv_bfloat16 g_xbh[(size_t)BN_ROWS * DIM];
__device__ __align__(16) __nv_bfloat16 g_xbl[(size_t)BN_ROWS * DIM];
__device__ __align__(16) __nv_bfloat16 g_abh[(size_t)BN_ROWS * DIM];
__device__ __align__(16) __nv_bfloat16 g_abl[(size_t)BN_ROWS * DIM];
// transposed+split weights [n][k]: [0]=W_qk, [1]=W_v, [2]=W_out
__device__ __align__(16) __nv_bfloat16 g_Wth[(size_t)3 * DIM * DIM];
__device__ __align__(16) __nv_bfloat16 g_Wtl[(size_t)3 * DIM * DIM];

// ---------------- helpers ----------------
__device__ __forceinline__ uint32_t f2tf32(float x) {
    uint32_t r;
    asm("cvt.rna.tf32.f32 %0, %1;" : "=r"(r) : "f"(x));
    return r;
}

__device__ __forceinline__ void mma_tf32(float c[4], const uint32_t a[4], const uint32_t b[2]) {
    asm volatile(
        "mma.sync.aligned.m16n8k8.row.col.f32.tf32.tf32.f32 "
        "{%0,%1,%2,%3}, {%4,%5,%6,%7}, {%8,%9}, {%0,%1,%2,%3};"
        : "+f"(c[0]), "+f"(c[1]), "+f"(c[2]), "+f"(c[3])
        : "r"(a[0]), "r"(a[1]), "r"(a[2]), "r"(a[3]), "r"(b[0]), "r"(b[1]));
}

__device__ __forceinline__ void mma_bf16(float c[4], const uint32_t a[4], const uint32_t b[2]) {
    asm volatile(
        "mma.sync.aligned.m16n8k16.row.col.f32.bf16.bf16.f32 "
        "{%0,%1,%2,%3}, {%4,%5,%6,%7}, {%8,%9}, {%0,%1,%2,%3};"
        : "+f"(c[0]), "+f"(c[1]), "+f"(c[2]), "+f"(c[3])
        : "r"(a[0]), "r"(a[1]), "r"(a[2]), "r"(a[3]), "r"(b[0]), "r"(b[1]));
}

__device__ __forceinline__ uint32_t smem_u32(const void* p) {
    uint32_t a;
    asm("{ .reg .u64 t; cvta.to.shared.u64 t, %1; cvt.u32.u64 %0, t; }" : "=r"(a) : "l"(p));
    return a;
}

__device__ __forceinline__ void cp16(uint32_t dst, const void* src) {
    asm volatile("cp.async.cg.shared.global [%0], [%1], 16;" :: "r"(dst), "l"(src) : "memory");
}
#define CP_COMMIT() asm volatile("cp.async.commit_group;" ::: "memory")
#define CP_WAIT1()  asm volatile("cp.async.wait_group 1;" ::: "memory")
#define CP_WAIT0()  asm volatile("cp.async.wait_group 0;" ::: "memory")

__device__ __forceinline__ void bf16_split2(float a, float b, uint32_t& h, uint32_t& l) {
    __nv_bfloat162 hp, lp;
    hp.x = __float2bfloat16(a); hp.y = __float2bfloat16(b);
    lp.x = __float2bfloat16(a - __bfloat162float(hp.x));
    lp.y = __float2bfloat16(b - __bfloat162float(hp.y));
    h = *reinterpret_cast<uint32_t*>(&hp);
    l = *reinterpret_cast<uint32_t*>(&lp);
}

// ======================= prep kernels =======================
__global__ __launch_bounds__(256)
void splitx_kernel(const float* __restrict__ X,
                   __nv_bfloat16* __restrict__ H, __nv_bfloat16* __restrict__ L)
{
    size_t i = ((size_t)blockIdx.x * 256 + threadIdx.x) * 8;
    float4 a = *(const float4*)(X + i);
    float4 b = *(const float4*)(X + i + 4);
    uint4 uh, ul;
    bf16_split2(a.x, a.y, uh.x, ul.x);
    bf16_split2(a.z, a.w, uh.y, ul.y);
    bf16_split2(b.x, b.y, uh.z, ul.z);
    bf16_split2(b.z, b.w, uh.w, ul.w);
    *(uint4*)(H + i) = uh;
    *(uint4*)(L + i) = ul;
}

__global__ __launch_bounds__(256)
void wprep_kernel(const float* __restrict__ W,
                  __nv_bfloat16* __restrict__ Wh, __nv_bfloat16* __restrict__ Wl)
{
    __shared__ float t[32][33];
    const int tx = threadIdx.x & 31, ty = threadIdx.x >> 5;
    const int n0 = blockIdx.x * 32, k0 = blockIdx.y * 32;
    #pragma unroll
    for (int i = 0; i < 4; i++)
        t[ty + 8 * i][tx] = W[(size_t)(k0 + ty + 8 * i) * 1024 + n0 + tx];
    __syncthreads();
    #pragma unroll
    for (int i = 0; i < 4; i++) {
        float x = t[tx][ty + 8 * i];
        __nv_bfloat16 h = __float2bfloat16(x);
        __nv_bfloat16 l = __float2bfloat16(x - __bfloat162float(h));
        size_t o = (size_t)(n0 + ty + 8 * i) * 1024 + k0 + tx;
        Wh[o] = h; Wl[o] = l;
    }
}

// ======================= bf16 3-term GEMM (R13, unchanged) =======================
#define RS 20
#define TILE_W (128*RS)
#define STG_W (4*TILE_W)
#define STG_B (STG_W*4)
#define GEMM_SMEM_BYTES (2*STG_B)  // 81920

__global__ __launch_bounds__(256, 2)
void gemm_bf3_kernel(const __nv_bfloat16* __restrict__ Ahp,
                     const __nv_bfloat16* __restrict__ Alp,
                     const __nv_bfloat16* __restrict__ BH0, const __nv_bfloat16* __restrict__ BL0,
                     const __nv_bfloat16* __restrict__ BH1, const __nv_bfloat16* __restrict__ BL1,
                     const float* __restrict__ bias,
                     float* __restrict__ C0, float* __restrict__ C1,
                     int nx, int round_c)
{
    extern __shared__ uint32_t smg[];
    const uint32_t sb = smem_u32(smg);

    const int tid  = threadIdx.x;
    const int lane = tid & 31;
    const int w    = tid >> 5;
    const int wm   = w >> 2;
    const int wn   = w & 3;
    const int g    = lane >> 2;
    const int r    = lane & 3;

    int bx = blockIdx.x;
    const int by = blockIdx.y;
    const __nv_bfloat16* BH = BH0;
    const __nv_bfloat16* BL = BL0;
    float* C = C0;
    if (bx >= nx) { BH = BH1; BL = BL1; C = C1; bx -= nx; }
    const int cb = bx * 128;

    const __nv_bfloat16* AbH = Ahp + (size_t)(by * 128) * DIM;
    const __nv_bfloat16* AbL = Alp + (size_t)(by * 128) * DIM;
    const __nv_bfloat16* BbH = BH + (size_t)cb * DIM;
    const __nv_bfloat16* BbL = BL + (size_t)cb * DIM;

    #define CP_AB(k0, buf) do {                                                   \
        uint32_t base = sb + (uint32_t)(buf) * STG_B;                             \
        _Pragma("unroll")                                                         \
        for (int i = 0; i < 2; i++) {                                             \
            int idx = tid + 256 * i;                                              \
            int row = idx >> 2, ch = idx & 3;                                     \
            uint32_t d = base + (uint32_t)(row * RS + ch * 4) * 4;                \
            size_t s = (size_t)row * DIM + (k0) + ch * 8;                         \
            cp16(d,                  AbH + s);                                    \
            cp16(d + TILE_W * 4,     AbL + s);                                    \
            cp16(d + 2 * TILE_W * 4, BbH + s);                                    \
            cp16(d + 3 * TILE_W * 4, BbL + s);                                    \
        }                                                                         \
        CP_COMMIT();                                                              \
    } while (0)

    float acc[4][4][4];
    #pragma unroll
    for (int mt = 0; mt < 4; mt++)
        #pragma unroll
        for (int nt = 0; nt < 4; nt++)
            #pragma unroll
            for (int i = 0; i < 4; i++) acc[mt][nt][i] = 0.f;

    const int NIT = DIM / 32;   // 32

    CP_AB(0, 0);
    CP_WAIT0();
    __syncthreads();

    for (int it = 0; it < NIT; it++) {
        const int cur = it & 1;
        const bool more = (it + 1 < NIT);
        if (more) CP_AB((it + 1) * 32, cur ^ 1);

        const uint32_t* Ah = smg + cur * STG_W;
        const uint32_t* Al = Ah + TILE_W;
        const uint32_t* Bh = Al + TILE_W;
        const uint32_t* Bl = Bh + TILE_W;

        #pragma unroll
        for (int kb = 0; kb < 16; kb += 8) {
            uint32_t bh[4][2], bl[4][2];
            #pragma unroll
            for (int nt = 0; nt < 4; nt++) {
                int n0 = (wn * 32 + nt * 8 + g) * RS + kb;
                bh[nt][0] = Bh[n0 + r];
                bh[nt][1] = Bh[n0 + r + 4];
                bl[nt][0] = Bl[n0 + r];
                bl[nt][1] = Bl[n0 + r + 4];
            }
            #pragma unroll
            for (int mt = 0; mt < 4; mt++) {
                int m0 = (wm * 64 + mt * 16 + g) * RS + kb;
                int m8 = m0 + 8 * RS;
                uint32_t aH[4], aL[4];
                aH[0] = Ah[m0 + r];     aH[1] = Ah[m8 + r];
                aH[2] = Ah[m0 + r + 4]; aH[3] = Ah[m8 + r + 4];
                aL[0] = Al[m0 + r];     aL[1] = Al[m8 + r];
                aL[2] = Al[m0 + r + 4]; aL[3] = Al[m8 + r + 4];
                #pragma unroll
                for (int nt = 0; nt < 4; nt++) {
                    mma_bf16(acc[mt][nt], aH, bl[nt]);
                    mma_bf16(acc[mt][nt], aL, bh[nt]);
                    mma_bf16(acc[mt][nt], aH, bh[nt]);
                }
            }
        }

        if (more) CP_WAIT0();
        __syncthreads();
    }

    #pragma unroll
    for (int mt = 0; mt < 4; mt++) {
        int row0 = by * 128 + wm * 64 + mt * 16 + g;
        #pragma unroll
        for (int nt = 0; nt < 4; nt++) {
            int col = cb + wn * 32 + nt * 8 + r * 2;
            float b0 = 0.f, b1 = 0.f;
            if (bias != nullptr) { b0 = bias[col]; b1 = bias[col + 1]; }
            float2 v0 = make_float2(acc[mt][nt][0] + b0, acc[mt][nt][1] + b1);
            float2 v1 = make_float2(acc[mt][nt][2] + b0, acc[mt][nt][3] + b1);
            if (round_c) {
                v0.x = __uint_as_float(f2tf32(v0.x));
                v0.y = __uint_as_float(f2tf32(v0.y));
                v1.x = __uint_as_float(f2tf32(v1.x));
                v1.y = __uint_as_float(f2tf32(v1.y));
            }
            *(float2*)(C + (size_t)row0 * DIM + col)       = v0;
            *(float2*)(C + (size_t)(row0 + 8) * DIM + col) = v1;
        }
    }
}

// ======================= Flash attention (R13 shape; fused bf16-split epilogue) ========
#define AKT 64
#define QT  64
#define KS_W 68
#define VS_W 136
#define KS_BYTES (AKT * KS_W * 4)
#define VS_BYTES (AKT * VS_W * 4)
#define BUF_BYTES (KS_BYTES + VS_BYTES)
#define BUF_WORDS (BUF_BYTES / 4)
#define ATTN_SMEM_BYTES (2 * BUF_BYTES + 128)   // 104576
#define OB_STRIDE 132                            // 64x128 f32 bounce tile, conflict-free

__global__ __launch_bounds__(128, 2)
void attn_tc_kernel(const float* __restrict__ qk, const float* __restrict__ vbuf,
                    const float* __restrict__ conv,
                    __nv_bfloat16* __restrict__ AH, __nv_bfloat16* __restrict__ AL)
{
    extern __shared__ uint32_t smu[];
    float* Cv = (float*)(smu + 2 * BUF_WORDS);
    const uint32_t sbase = smem_u32(smu);

    const int tid  = threadIdx.x;
    const int lane = tid & 31;
    const int w    = tid >> 5;
    const int g    = lane >> 2;
    const int r    = lane & 3;
    const int h    = blockIdx.y;
    const int b    = blockIdx.z;
    const int i0   = blockIdx.x * QT;
    const uint32_t full = 0xffffffffu;

    if (tid < 2 * MAX_POS + 1) Cv[tid] = conv[h * (2 * MAX_POS + 1) + tid];

    uint32_t qa[8][4];
    {
        const uint32_t* q0 = (const uint32_t*)(qk + (size_t)(b * N + i0 + w * 16 + g) * DIM + h * DQK);
        const uint32_t* q1 = q0 + 8 * DIM;
        #pragma unroll
        for (int kt = 0; kt < 8; kt++) {
            qa[kt][0] = q0[kt * 8 + r];
            qa[kt][1] = q1[kt * 8 + r];
            qa[kt][2] = q0[kt * 8 + r + 4];
            qa[kt][3] = q1[kt * 8 + r + 4];
        }
    }

    #define STAGE(j0v, bb)                                                        \
        do {                                                                      \
            uint32_t kb = sbase + (bb) * BUF_BYTES;                               \
            const float* ks = qk + (size_t)(b * N + (j0v)) * DIM                  \
                              + HEADS * DQK + h * DQK;                            \
            _Pragma("unroll")                                                     \
            for (int i = 0; i < 8; i++) {                                         \
                int idx = tid + 128 * i;                                          \
                int row = idx >> 4, c4 = (idx & 15) << 2;                         \
                cp16(kb + (uint32_t)(row * KS_W + c4) * 4,                        \
                     ks + (size_t)row * DIM + c4);                                \
            }                                                                     \
            uint32_t vb = kb + KS_BYTES;                                          \
            const float* vs = vbuf + (size_t)(b * N + (j0v)) * DIM + h * DV;      \
            _Pragma("unroll")                                                     \
            for (int i = 0; i < 16; i++) {                                        \
                int idx = tid + 128 * i;                                          \
                int row = idx >> 5, c4 = (idx & 31) << 2;                         \
                cp16(vb + (uint32_t)(row * VS_W + c4) * 4,                        \
                     vs + (size_t)row * DIM + c4);                                \
            }                                                                     \
            CP_COMMIT();                                                          \
        } while (0)

    float l_lo = 0.f, l_hi = 0.f;
    float oacc[8][2][4];
    #pragma unroll
    for (int mt = 0; mt < 8; mt++)
        #pragma unroll
        for (int nt = 0; nt < 2; nt++)
            #pragma unroll
            for (int i = 0; i < 4; i++) oacc[mt][nt][i] = 0.f;

    const int ilo = i0 + w * 16 + g;
    const int ihi = ilo + 8;
    const int srcA = (lane & ~3) | (r >> 1);
    const int srcB = srcA + 2;
    const bool pr  = (r & 1);

    STAGE(0, 0);

    const int NJ = N / AKT;
    for (int jt = 0; jt < NJ; jt++) {
        const int buf = jt & 1;
        if (jt + 1 < NJ) { STAGE((jt + 1) * AKT, buf ^ 1); CP_WAIT1(); }
        else             { CP_WAIT0(); }
        __syncthreads();

        const uint32_t* Ks = smu + buf * BUF_WORDS;
        const uint32_t* Vs = Ks + KS_BYTES / 4;
        const int j0 = jt * AKT;

        float sacc[8][4];
        #pragma unroll
        for (int nt = 0; nt < 8; nt++)
            #pragma unroll
            for (int i = 0; i < 4; i++) sacc[nt][i] = 0.f;

        #pragma unroll
        for (int kt = 0; kt < 8; kt++) {
            #pragma unroll
            for (int nt = 0; nt < 8; nt++) {
                uint32_t bf[2];
                bf[0] = Ks[(nt * 8 + g) * KS_W + kt * 8 + r];
                bf[1] = Ks[(nt * 8 + g) * KS_W + kt * 8 + r + 4];
                mma_tf32(sacc[nt], qa[kt], bf);
            }
        }

        uint32_t Pf[8][4];
        float ls_lo = 0.f, ls_hi = 0.f;
        #pragma unroll
        for (int nt = 0; nt < 8; nt++) {
            int j = j0 + nt * 8 + 2 * r;
            int d00 = min(max(j     - ilo, -MAX_POS), MAX_POS) + MAX_POS;
            int d01 = min(max(j + 1 - ilo, -MAX_POS), MAX_POS) + MAX_POS;
            int d10 = min(max(j     - ihi, -MAX_POS), MAX_POS) + MAX_POS;
            int d11 = min(max(j + 1 - ihi, -MAX_POS), MAX_POS) + MAX_POS;
            float p0 = __expf(sacc[nt][0] * SCALE + Cv[d00]);
            float p1 = __expf(sacc[nt][1] * SCALE + Cv[d01]);
            float p2 = __expf(sacc[nt][2] * SCALE + Cv[d10]);
            float p3 = __expf(sacc[nt][3] * SCALE + Cv[d11]);
            ls_lo += p0 + p1;
            ls_hi += p2 + p3;
            Pf[nt][0] = f2tf32(p0); Pf[nt][1] = f2tf32(p1);
            Pf[nt][2] = f2tf32(p2); Pf[nt][3] = f2tf32(p3);
        }
        l_lo += ls_lo;
        l_hi += ls_hi;

        #pragma unroll
        for (int kt = 0; kt < 8; kt++) {
            uint32_t s0 = __shfl_sync(full, Pf[kt][0], srcA);
            uint32_t s1 = __shfl_sync(full, Pf[kt][1], srcA);
            uint32_t t0 = __shfl_sync(full, Pf[kt][0], srcB);
            uint32_t t1 = __shfl_sync(full, Pf[kt][1], srcB);
            uint32_t bl2[2];
            bl2[0] = pr ? s1 : s0;
            bl2[1] = pr ? t1 : t0;
            uint32_t s2 = __shfl_sync(full, Pf[kt][2], srcA);
            uint32_t s3 = __shfl_sync(full, Pf[kt][3], srcA);
            uint32_t t2 = __shfl_sync(full, Pf[kt][2], srcB);
            uint32_t t3 = __shfl_sync(full, Pf[kt][3], srcB);
            uint32_t bh2[2];
            bh2[0] = pr ? s3 : s2;
            bh2[1] = pr ? t3 : t2;
            #pragma unroll
            for (int mt = 0; mt < 8; mt++) {
                uint32_t vf[4];
                vf[0] = Vs[(kt * 8 + r)     * VS_W + mt * 16 + g];
                vf[1] = Vs[(kt * 8 + r)     * VS_W + mt * 16 + 8 + g];
                vf[2] = Vs[(kt * 8 + r + 4) * VS_W + mt * 16 + g];
                vf[3] = Vs[(kt * 8 + r + 4) * VS_W + mt * 16 + 8 + g];
                mma_tf32(oacc[mt][0], vf, bl2);
                mma_tf32(oacc[mt][1], vf, bh2);
            }
        }
        __syncthreads();
    }

    // ---- epilogue: normalize -> smem bounce (conflict-free) -> coalesced bf16 h/l ----
    l_lo += __shfl_xor_sync(full, l_lo, 1);
    l_lo += __shfl_xor_sync(full, l_lo, 2);
    l_hi += __shfl_xor_sync(full, l_hi, 1);
    l_hi += __shfl_xor_sync(full, l_hi, 2);
    float inv_lo = 1.f / l_lo;
    float inv_hi = 1.f / l_hi;
    float iq0  = __shfl_sync(full, inv_lo, 8 * r);
    float iq1  = __shfl_sync(full, inv_lo, 8 * r + 4);
    float iq0h = __shfl_sync(full, inv_hi, 8 * r);
    float iq1h = __shfl_sync(full, inv_hi, 8 * r + 4);

    float* Ob = (float*)smu;   // reuse K/V smem: 64 rows x 128 cols, stride 132
    // rows are CTA-relative: warp w owns rows w*16 .. w*16+15
    {
        const int rw0 = w * 16;
        #pragma unroll
        for (int mt = 0; mt < 8; mt++) {
            int c0 = mt * 16 + g;
            Ob[(rw0 + 2 * r    ) * OB_STRIDE + c0    ] = oacc[mt][0][0] * iq0;
            Ob[(rw0 + 2 * r + 1) * OB_STRIDE + c0    ] = oacc[mt][0][1] * iq1;
            Ob[(rw0 + 2 * r    ) * OB_STRIDE + c0 + 8] = oacc[mt][0][2] * iq0;
            Ob[(rw0 + 2 * r + 1) * OB_STRIDE + c0 + 8] = oacc[mt][0][3] * iq1;
            Ob[(rw0 + 8 + 2 * r    ) * OB_STRIDE + c0    ] = oacc[mt][1][0] * iq0h;
            Ob[(rw0 + 8 + 2 * r + 1) * OB_STRIDE + c0    ] = oacc[mt][1][1] * iq1h;
            Ob[(rw0 + 8 + 2 * r    ) * OB_STRIDE + c0 + 8] = oacc[mt][1][2] * iq0h;
            Ob[(rw0 + 8 + 2 * r + 1) * OB_STRIDE + c0 + 8] = oacc[mt][1][3] * iq1h;
        }
    }
    __syncthreads();

    // coalesced split-store: 64 rows x 128 cols = 8192 elems; 128 thr x 16 iters x 4
    #pragma unroll
    for (int i = 0; i < 16; i++) {
        int idx = tid + 128 * i;
        int row = idx >> 5;            // 0..63
        int c4  = (idx & 31) << 2;     // 0..124
        const float* src = &Ob[row * OB_STRIDE + c4];
        uint32_t h0, h1, l0, l1;
        bf16_split2(src[0], src[1], h0, l0);
        bf16_split2(src[2], src[3], h1, l1);
        size_t o = (size_t)(b * N + i0 + row) * DIM + h * DV + c4;
        *(uint2*)(AH + o) = make_uint2(h0, h1);
        *(uint2*)(AL + o) = make_uint2(l0, l1);
    }
}

// ======================= launch =======================
extern "C" void kernel_launch(void* const* d_in, const int* in_sizes, int n_in,
                              void* d_out, int out_size)
{
    const float* x     = (const float*)d_in[0];
    // d_in[1] = mask (unused by the reference)
    const float* W_qk  = (const float*)d_in[2];
    const float* W_v   = (const float*)d_in[3];
    const float* W_out = (const float*)d_in[4];
    const float* b_out = (const float*)d_in[5];
    const float* conv  = (const float*)d_in[6];
    float* out = (float*)d_out;

    float *qk_p, *v_p;
    cudaGetSymbolAddress((void**)&qk_p, g_qk);
    cudaGetSymbolAddress((void**)&v_p,  g_v);
    __nv_bfloat16 *xbh, *xbl, *abh, *abl, *wth, *wtl;
    cudaGetSymbolAddress((void**)&xbh, g_xbh);
    cudaGetSymbolAddress((void**)&xbl, g_xbl);
    cudaGetSymbolAddress((void**)&abh, g_abh);
    cudaGetSymbolAddress((void**)&abl, g_abl);
    cudaGetSymbolAddress((void**)&wth, g_Wth);
    cudaGetSymbolAddress((void**)&wtl, g_Wtl);

    cudaFuncSetAttribute(gemm_bf3_kernel, cudaFuncAttributeMaxDynamicSharedMemorySize,
                         GEMM_SMEM_BYTES);
    cudaFuncSetAttribute(attn_tc_kernel, cudaFuncAttributeMaxDynamicSharedMemorySize,
                         ATTN_SMEM_BYTES);

    const size_t WSZ = (size_t)DIM * DIM;

    // 0) prep: split x; transpose+split weights
    splitx_kernel<<<BN_ROWS * DIM / 2048, 256>>>(x, xbh, xbl);
    dim3 wgrid(32, 32);
    wprep_kernel<<<wgrid, 256>>>(W_qk,  wth,           wtl);
    wprep_kernel<<<wgrid, 256>>>(W_v,   wth + WSZ,     wtl + WSZ);
    wprep_kernel<<<wgrid, 256>>>(W_out, wth + 2 * WSZ, wtl + 2 * WSZ);

    // 1+2) fused qkv (single launch): bx 0..7 -> g_qk (W_qk), bx 8..15 -> g_v (W_v)
    dim3 qkv_grid(16, 64);
    gemm_bf3_kernel<<<qkv_grid, 256, GEMM_SMEM_BYTES>>>(
        xbh, xbl, wth, wtl, wth + WSZ, wtl + WSZ, nullptr, qk_p, v_p, 8, 1);

    // 3) attention -> abh/abl directly (bf16 h/l via smem bounce)
    dim3 attn_grid(N / QT, HEADS, B);   // (32, 8, 4)
    attn_tc_kernel<<<attn_grid, 128, ATTN_SMEM_BYTES>>>(qk_p, v_p, conv, abh, abl);

    // 4) out = ao @ W_out + b_out (full f32 output)
    dim3 out_grid(8, 64);
    gemm_bf3_kernel<<<out_grid, 256, GEMM_SMEM_BYTES>>>(
        abh, abl, wth + 2 * WSZ, wtl + 2 * WSZ, wth + 2 * WSZ, wtl + 2 * WSZ,
        b_out, out, out, 8, 0);
}